// round 4
// baseline (speedup 1.0000x reference)
#include <cuda_runtime.h>
#include <cstdint>
#include <cstddef>

#define S_LEN 2048
#define BATCH 512
#define VDIM  29
#define HDIM  128
#define KTOT  160            // 128 (h) + 29 (x) padded to 160
#define NWARP 8
#define KC    (KTOT / NWARP) // 20 k's per warp
#define ROWS  4

// intermediate encoder state (static device scratch — no allocation)
__device__ float g_enc[BATCH * HDIM];

typedef unsigned long long ull;

__device__ __forceinline__ ull pack2(float lo, float hi) {
    ull r; asm("mov.b64 %0, {%1, %2};" : "=l"(r) : "f"(lo), "f"(hi)); return r;
}
__device__ __forceinline__ ull fma2(ull a, ull b, ull c) {
    ull d; asm("fma.rn.f32x2 %0, %1, %2, %3;" : "=l"(d) : "l"(a), "l"(b), "l"(c)); return d;
}
__device__ __forceinline__ void unpack2(ull v, float& lo, float& hi) {
    asm("mov.b64 {%0, %1}, %2;" : "=f"(lo), "=f"(hi) : "l"(v));
}

// ---------------------------------------------------------------------------
// Encoder: persistent kernel. 128 CTAs x 4 batch rows x 256 threads.
// Per step: pre[r][j] = sum_k Wc[j][k] * g[k][r] ; h = tanh(pre + bias)
//   where g = concat(h, x_t) (KTOT padded), Wc = [We_hh | We_ih].
// Warp w handles k in [w*20, w*20+20); lane handles cols 4*lane..4*lane+3,
// all 4 rows in registers (f32x2 pairs). 8-way k-partials reduced via SMEM.
// ---------------------------------------------------------------------------
__global__ void __launch_bounds__(256, 1) enc_kernel(
    const float* __restrict__ x, const float* __restrict__ We_ih,
    const float* __restrict__ We_hh, const float* __restrict__ be_ih,
    const float* __restrict__ be_hh)
{
    extern __shared__ float sm[];
    float* Wt    = sm;                        // [KTOT][HDIM] k-major
    float* gb    = Wt + KTOT * HDIM;          // [2][KTOT][ROWS] double-buffered
    float* red   = gb + 2 * KTOT * ROWS;      // [NWARP*4][HDIM] partials
    float* biasE = red + NWARP * 4 * HDIM;    // [HDIM]

    const int tid  = threadIdx.x;
    const int warp = tid >> 5, lane = tid & 31;
    const int rowbase = blockIdx.x * ROWS;

    // Build k-major combined weight: Wt[k][j]
    for (int i = tid; i < KTOT * HDIM; i += 256) {
        int k = i >> 7, j = i & (HDIM - 1);
        float w = 0.f;
        if (k < HDIM)             w = We_hh[j * HDIM + k];
        else if (k < HDIM + VDIM) w = We_ih[j * VDIM + (k - HDIM)];
        Wt[i] = w;
    }
    if (tid < HDIM) biasE[tid] = be_ih[tid] + be_hh[tid];
    for (int i = tid; i < 2 * KTOT * ROWS; i += 256) gb[i] = 0.f;  // h=0, pads=0
    __syncthreads();
    // x_0 into buffer 0's x-region
    if (tid < ROWS * VDIM) {
        int r = tid / VDIM, v = tid - r * VDIM;
        gb[(HDIM + v) * ROWS + r] = x[((size_t)(rowbase + r) * S_LEN) * VDIM + v];
    }
    __syncthreads();

    const int k0 = warp * KC;

    for (int t = 0; t < S_LEN; ++t) {
        float* g  = gb + (t & 1) * (KTOT * ROWS);
        float* gn = gb + ((t & 1) ^ 1) * (KTOT * ROWS);

        // prefetch next step's x (latency hidden under the GEMV)
        float xr = 0.f; int xslot = -1;
        if (tid < ROWS * VDIM && t + 1 < S_LEN) {
            int r = tid / VDIM, v = tid - r * VDIM;
            xr = x[((size_t)(rowbase + r) * S_LEN + (t + 1)) * VDIM + v];
            xslot = (HDIM + v) * ROWS + r;
        }

        ull a01[4] = {0, 0, 0, 0};   // rows 0,1 packed, cols 0..3
        ull a23[4] = {0, 0, 0, 0};   // rows 2,3 packed
        #pragma unroll
        for (int kk = 0; kk < KC; ++kk) {
            const int k = k0 + kk;
            const float4 w4 = *(const float4*)(Wt + k * HDIM + 4 * lane); // conflict-free
            const ull g01 = *(const ull*)(g + k * ROWS);                  // broadcast
            const ull g23 = *(const ull*)(g + k * ROWS + 2);              // broadcast
            ull w;
            w = pack2(w4.x, w4.x); a01[0] = fma2(w, g01, a01[0]); a23[0] = fma2(w, g23, a23[0]);
            w = pack2(w4.y, w4.y); a01[1] = fma2(w, g01, a01[1]); a23[1] = fma2(w, g23, a23[1]);
            w = pack2(w4.z, w4.z); a01[2] = fma2(w, g01, a01[2]); a23[2] = fma2(w, g23, a23[2]);
            w = pack2(w4.w, w4.w); a01[3] = fma2(w, g01, a01[3]); a23[3] = fma2(w, g23, a23[3]);
        }
        float p0[4], p1[4], p2[4], p3[4];
        #pragma unroll
        for (int c = 0; c < 4; ++c) {
            unpack2(a01[c], p0[c], p1[c]);
            unpack2(a23[c], p2[c], p3[c]);
        }
        {   // store k-partials, conflict-free STS.128
            float* rb = red + (warp * 4) * HDIM + 4 * lane;
            *(float4*)(rb)            = make_float4(p0[0], p0[1], p0[2], p0[3]);
            *(float4*)(rb + HDIM)     = make_float4(p1[0], p1[1], p1[2], p1[3]);
            *(float4*)(rb + 2 * HDIM) = make_float4(p2[0], p2[1], p2[2], p2[3]);
            *(float4*)(rb + 3 * HDIM) = make_float4(p3[0], p3[1], p3[2], p3[3]);
        }
        if (xslot >= 0) gn[xslot] = xr;  // stage x_{t+1} (region idle since t-1)
        __syncthreads();

        // finalize: thread j sums 8 partials per row, tanh, repack as float4-of-rows
        if (tid < HDIM) {
            const int j = tid;
            float hv[4];
            #pragma unroll
            for (int r = 0; r < 4; ++r) {
                float s = biasE[j];
                #pragma unroll
                for (int kc = 0; kc < NWARP; ++kc) s += red[(kc * 4 + r) * HDIM + j];
                hv[r] = tanhf(s);
            }
            *(float4*)(gn + j * ROWS) = make_float4(hv[0], hv[1], hv[2], hv[3]);
            if (t == S_LEN - 1) {
                #pragma unroll
                for (int r = 0; r < 4; ++r) g_enc[(rowbase + r) * HDIM + j] = hv[r];
            }
        }
        __syncthreads();
    }
}

// ---------------------------------------------------------------------------
// Decoder: one warp per batch row. 29-dim recurrence, Wd_hh row in registers,
// h broadcast via shfl. dec_in computed once per row from g_enc.
// ---------------------------------------------------------------------------
__global__ void __launch_bounds__(256) dec_kernel(
    const float* __restrict__ Wd_ih, const float* __restrict__ Wd_hh,
    const float* __restrict__ bd_ih, const float* __restrict__ bd_hh,
    float* __restrict__ out)
{
    const int warp = threadIdx.x >> 5, lane = threadIdx.x & 31;
    const int b = blockIdx.x * 8 + warp;
    const float* er = g_enc + b * HDIM;
    float e0 = er[lane], e1 = er[32 + lane], e2 = er[64 + lane], e3 = er[96 + lane];
    const bool act = lane < VDIM;
    const int vl = act ? lane : 0;   // clamp so inactive lanes do harmless loads

    float Wr[VDIM];
    #pragma unroll
    for (int u = 0; u < VDIM; ++u) Wr[u] = Wd_hh[vl * VDIM + u];

    float din = bd_ih[vl] + bd_hh[vl];
    {   // dec_in[v] = sum_k Wd_ih[v][k] * enc[b][k]
        const float* wi = Wd_ih + vl * HDIM;
        float s0 = 0, s1 = 0, s2 = 0, s3 = 0;
        #pragma unroll
        for (int k = 0; k < 32; ++k) {
            s0 += wi[k]      * __shfl_sync(0xffffffffu, e0, k);
            s1 += wi[32 + k] * __shfl_sync(0xffffffffu, e1, k);
            s2 += wi[64 + k] * __shfl_sync(0xffffffffu, e2, k);
            s3 += wi[96 + k] * __shfl_sync(0xffffffffu, e3, k);
        }
        din += (s0 + s1) + (s2 + s3);
    }

    float h = 0.f;
    float* orow = out + (size_t)b * S_LEN * VDIM + lane;
    for (int s = 0; s < S_LEN; ++s) {
        float q0 = din, q1 = 0.f, q2 = 0.f, q3 = 0.f;
        #pragma unroll
        for (int u = 0; u < 28; u += 4) {
            q0 += Wr[u]     * __shfl_sync(0xffffffffu, h, u);
            q1 += Wr[u + 1] * __shfl_sync(0xffffffffu, h, u + 1);
            q2 += Wr[u + 2] * __shfl_sync(0xffffffffu, h, u + 2);
            q3 += Wr[u + 3] * __shfl_sync(0xffffffffu, h, u + 3);
        }
        q0 += Wr[28] * __shfl_sync(0xffffffffu, h, 28);
        h = tanhf((q0 + q1) + (q2 + q3));
        if (act) orow[(size_t)s * VDIM] = h;
    }
}

// ---------------------------------------------------------------------------
extern "C" void kernel_launch(void* const* d_in, const int* in_sizes, int n_in,
                              void* d_out, int out_size) {
    const float* x     = (const float*)d_in[0];
    const float* We_ih = (const float*)d_in[1];
    const float* We_hh = (const float*)d_in[2];
    const float* be_ih = (const float*)d_in[3];
    const float* be_hh = (const float*)d_in[4];
    const float* Wd_ih = (const float*)d_in[5];
    const float* Wd_hh = (const float*)d_in[6];
    const float* bd_ih = (const float*)d_in[7];
    const float* bd_hh = (const float*)d_in[8];
    float* out = (float*)d_out;

    const int smem = (KTOT * HDIM + 2 * KTOT * ROWS + NWARP * 4 * HDIM + HDIM) * 4; // 103936 B
    cudaFuncSetAttribute(enc_kernel, cudaFuncAttributeMaxDynamicSharedMemorySize, smem);

    enc_kernel<<<BATCH / ROWS, 256, smem>>>(x, We_ih, We_hh, be_ih, be_hh);
    dec_kernel<<<BATCH / 8, 256>>>(Wd_ih, Wd_hh, bd_ih, bd_hh, out);
}

// round 5
// speedup vs baseline: 1.2437x; 1.2437x over previous
#include <cuda_runtime.h>
#include <cstdint>
#include <cstddef>

#define S_LEN 2048
#define BATCH 512
#define VDIM  29
#define HDIM  128
#define KTOT  160            // 128 (h) + 29 (x) padded to 160
#define NWARP 8
#define KC    (KTOT / NWARP) // 20 k's per warp
#define ROWS  4

// intermediate encoder state (static device scratch — no allocation)
__device__ float g_enc[BATCH * HDIM];

typedef unsigned long long ull;

__device__ __forceinline__ ull pack2(float lo, float hi) {
    ull r; asm("mov.b64 %0, {%1, %2};" : "=l"(r) : "f"(lo), "f"(hi)); return r;
}
__device__ __forceinline__ ull fma2(ull a, ull b, ull c) {
    ull d; asm("fma.rn.f32x2 %0, %1, %2, %3;" : "=l"(d) : "l"(a), "l"(b), "l"(c)); return d;
}
__device__ __forceinline__ void unpack2(ull v, float& lo, float& hi) {
    asm("mov.b64 {%0, %1}, %2;" : "=f"(lo), "=f"(hi) : "l"(v));
}

// ---------------------------------------------------------------------------
// Encoder: persistent kernel. 128 CTAs x 4 batch rows x 256 threads.
// Warp w owns k in [w*20, w*20+20); lane owns cols 4*lane..4*lane+3 with the
// 20x4 weight tile held in REGISTERS (loaded once). Per step only g (state)
// is broadcast from SMEM; 8-way k-partials reduced via SMEM by all 256 thr.
// ---------------------------------------------------------------------------
__global__ void __launch_bounds__(256, 1) enc_kernel(
    const float* __restrict__ x, const float* __restrict__ We_ih,
    const float* __restrict__ We_hh, const float* __restrict__ be_ih,
    const float* __restrict__ be_hh)
{
    extern __shared__ float sm[];
    float* Wt    = sm;                        // [KTOT][HDIM] staging (dead after init)
    float* gb    = Wt + KTOT * HDIM;          // [2][KTOT][ROWS] double-buffered
    float* red   = gb + 2 * KTOT * ROWS;      // [NWARP*4][HDIM] partials
    float* biasE = red + NWARP * 4 * HDIM;    // [HDIM]

    const int tid  = threadIdx.x;
    const int warp = tid >> 5, lane = tid & 31;
    const int rowbase = blockIdx.x * ROWS;

    // Build k-major combined weight in SMEM (coalesced-ish), then lift to regs
    for (int i = tid; i < KTOT * HDIM; i += 256) {
        int k = i >> 7, j = i & (HDIM - 1);
        float w = 0.f;
        if (k < HDIM)             w = We_hh[j * HDIM + k];
        else if (k < HDIM + VDIM) w = We_ih[j * VDIM + (k - HDIM)];
        Wt[i] = w;
    }
    if (tid < HDIM) biasE[tid] = be_ih[tid] + be_hh[tid];
    for (int i = tid; i < 2 * KTOT * ROWS; i += 256) gb[i] = 0.f;  // h=0, pads=0
    __syncthreads();

    const int k0 = warp * KC;
    float4 Wreg[KC];                           // 80 registers of loop-invariant W
    #pragma unroll
    for (int kk = 0; kk < KC; ++kk)
        Wreg[kk] = *(const float4*)(Wt + (k0 + kk) * HDIM + 4 * lane);

    // x_0 into buffer 0's x-region
    if (tid < ROWS * VDIM) {
        int r = tid / VDIM, v = tid - r * VDIM;
        gb[(HDIM + v) * ROWS + r] = x[((size_t)(rowbase + r) * S_LEN) * VDIM + v];
    }
    __syncthreads();

    const int jred = tid & (HDIM - 1);         // reduction: 256 thr = 128 j x 2 row-halves
    const int rh   = tid >> 7;                 // 0 -> rows 0,1 ; 1 -> rows 2,3

    for (int t = 0; t < S_LEN; ++t) {
        float* g  = gb + (t & 1) * (KTOT * ROWS);
        float* gn = gb + ((t & 1) ^ 1) * (KTOT * ROWS);

        // prefetch next step's x (latency hidden under the GEMV)
        float xr = 0.f; int xslot = -1;
        if (tid < ROWS * VDIM && t + 1 < S_LEN) {
            int r = tid / VDIM, v = tid - r * VDIM;
            xr = x[((size_t)(rowbase + r) * S_LEN + (t + 1)) * VDIM + v];
            xslot = (HDIM + v) * ROWS + r;
        }

        ull a01[4] = {0, 0, 0, 0};   // rows 0,1 packed, cols 0..3
        ull a23[4] = {0, 0, 0, 0};   // rows 2,3 packed
        #pragma unroll
        for (int kk = 0; kk < KC; ++kk) {
            const int k = k0 + kk;
            const float4 gg = *(const float4*)(g + k * ROWS);   // 16B broadcast
            const ull g01 = pack2(gg.x, gg.y);
            const ull g23 = pack2(gg.z, gg.w);
            const float4 w4 = Wreg[kk];                          // registers, 0 LDS
            ull w;
            w = pack2(w4.x, w4.x); a01[0] = fma2(w, g01, a01[0]); a23[0] = fma2(w, g23, a23[0]);
            w = pack2(w4.y, w4.y); a01[1] = fma2(w, g01, a01[1]); a23[1] = fma2(w, g23, a23[1]);
            w = pack2(w4.z, w4.z); a01[2] = fma2(w, g01, a01[2]); a23[2] = fma2(w, g23, a23[2]);
            w = pack2(w4.w, w4.w); a01[3] = fma2(w, g01, a01[3]); a23[3] = fma2(w, g23, a23[3]);
        }
        float p0[4], p1[4], p2[4], p3[4];
        #pragma unroll
        for (int c = 0; c < 4; ++c) {
            unpack2(a01[c], p0[c], p1[c]);
            unpack2(a23[c], p2[c], p3[c]);
        }
        {   // store k-partials, conflict-free STS.128
            float* rb = red + (warp * 4) * HDIM + 4 * lane;
            *(float4*)(rb)            = make_float4(p0[0], p0[1], p0[2], p0[3]);
            *(float4*)(rb + HDIM)     = make_float4(p1[0], p1[1], p1[2], p1[3]);
            *(float4*)(rb + 2 * HDIM) = make_float4(p2[0], p2[1], p2[2], p2[3]);
            *(float4*)(rb + 3 * HDIM) = make_float4(p3[0], p3[1], p3[2], p3[3]);
        }
        if (xslot >= 0) gn[xslot] = xr;  // stage x_{t+1} (region idle since t-1)
        __syncthreads();

        // finalize: 256 threads, each sums 8 partials for (j, 2 rows), tanh
        {
            const int r0 = rh * 2;
            float s0 = biasE[jred], s1 = s0;
            #pragma unroll
            for (int kc = 0; kc < NWARP; ++kc) {
                s0 += red[(kc * 4 + r0    ) * HDIM + jred];
                s1 += red[(kc * 4 + r0 + 1) * HDIM + jred];
            }
            float h0 = tanhf(s0), h1 = tanhf(s1);
            *(float2*)(gn + jred * ROWS + r0) = make_float2(h0, h1);
            if (t == S_LEN - 1) {
                g_enc[(rowbase + r0    ) * HDIM + jred] = h0;
                g_enc[(rowbase + r0 + 1) * HDIM + jred] = h1;
            }
        }
        __syncthreads();
    }
}

// ---------------------------------------------------------------------------
// Decoder: one warp per batch row, 128 CTAs x 4 warps (1 warp/SMSP, 128 SMs).
// dec_in is constant per row and spectral_radius(Wd_hh) ~ 0.58 < 1, so the
// recurrence reaches its fp32 fixed point bit-exactly in ~50-100 steps.
// Detect bitwise convergence and fill the remaining steps with the fixed
// point (coalesced stores). Falls back to the full 2048 steps if not reached.
// ---------------------------------------------------------------------------
__global__ void __launch_bounds__(128) dec_kernel(
    const float* __restrict__ Wd_ih, const float* __restrict__ Wd_hh,
    const float* __restrict__ bd_ih, const float* __restrict__ bd_hh,
    float* __restrict__ out)
{
    const int warp = threadIdx.x >> 5, lane = threadIdx.x & 31;
    const int b = blockIdx.x * 4 + warp;
    const float* er = g_enc + b * HDIM;
    float e0 = er[lane], e1 = er[32 + lane], e2 = er[64 + lane], e3 = er[96 + lane];
    const bool act = lane < VDIM;
    const int vl = act ? lane : 0;   // clamp so inactive lanes do harmless loads

    float Wr[VDIM];
    #pragma unroll
    for (int u = 0; u < VDIM; ++u) Wr[u] = Wd_hh[vl * VDIM + u];

    float din = bd_ih[vl] + bd_hh[vl];
    {   // dec_in[v] = sum_k Wd_ih[v][k] * enc[b][k]
        const float* wi = Wd_ih + vl * HDIM;
        float s0 = 0, s1 = 0, s2 = 0, s3 = 0;
        #pragma unroll
        for (int k = 0; k < 32; ++k) {
            s0 += wi[k]      * __shfl_sync(0xffffffffu, e0, k);
            s1 += wi[32 + k] * __shfl_sync(0xffffffffu, e1, k);
            s2 += wi[64 + k] * __shfl_sync(0xffffffffu, e2, k);
            s3 += wi[96 + k] * __shfl_sync(0xffffffffu, e3, k);
        }
        din += (s0 + s1) + (s2 + s3);
    }

    float h = 0.f;
    float* orow = out + (size_t)b * S_LEN * VDIM + lane;
    int s = 0;
    for (; s < S_LEN; ++s) {
        float q0 = din, q1 = 0.f, q2 = 0.f, q3 = 0.f;
        #pragma unroll
        for (int u = 0; u < 28; u += 4) {
            q0 += Wr[u]     * __shfl_sync(0xffffffffu, h, u);
            q1 += Wr[u + 1] * __shfl_sync(0xffffffffu, h, u + 1);
            q2 += Wr[u + 2] * __shfl_sync(0xffffffffu, h, u + 2);
            q3 += Wr[u + 3] * __shfl_sync(0xffffffffu, h, u + 3);
        }
        q0 += Wr[28] * __shfl_sync(0xffffffffu, h, 28);
        float hn = tanhf((q0 + q1) + (q2 + q3));
        if (act) orow[(size_t)s * VDIM] = hn;
        bool eq = (!act) || (__float_as_int(hn) == __float_as_int(h));
        h = hn;
        if (__all_sync(0xffffffffu, eq)) { ++s; break; }
    }
    // fixed point reached: all remaining outputs are bit-identical to h
    if (act) {
        for (; s + 3 < S_LEN; s += 4) {
            orow[(size_t)(s    ) * VDIM] = h;
            orow[(size_t)(s + 1) * VDIM] = h;
            orow[(size_t)(s + 2) * VDIM] = h;
            orow[(size_t)(s + 3) * VDIM] = h;
        }
        for (; s < S_LEN; ++s) orow[(size_t)s * VDIM] = h;
    }
}

// ---------------------------------------------------------------------------
extern "C" void kernel_launch(void* const* d_in, const int* in_sizes, int n_in,
                              void* d_out, int out_size) {
    const float* x     = (const float*)d_in[0];
    const float* We_ih = (const float*)d_in[1];
    const float* We_hh = (const float*)d_in[2];
    const float* be_ih = (const float*)d_in[3];
    const float* be_hh = (const float*)d_in[4];
    const float* Wd_ih = (const float*)d_in[5];
    const float* Wd_hh = (const float*)d_in[6];
    const float* bd_ih = (const float*)d_in[7];
    const float* bd_hh = (const float*)d_in[8];
    float* out = (float*)d_out;

    const int smem = (KTOT * HDIM + 2 * KTOT * ROWS + NWARP * 4 * HDIM + HDIM) * 4; // 103936 B
    cudaFuncSetAttribute(enc_kernel, cudaFuncAttributeMaxDynamicSharedMemorySize, smem);

    enc_kernel<<<BATCH / ROWS, 256, smem>>>(x, We_ih, We_hh, be_ih, be_hh);
    dec_kernel<<<BATCH / 4, 128>>>(Wd_ih, Wd_hh, bd_ih, bd_hh, out);
}